// round 16
// baseline (speedup 1.0000x reference)
#include <cuda_runtime.h>
#include <cuda_bf16.h>
#include <cstdint>

// Problem dims (fixed)
#define NN   8192
#define D0   128
#define D1   256
#define D2   256
#define QH   128
#define EPSV 1e-5f

// bigmm tiling: CTA 64x128, BK=64 (int8 bytes), 8 warps (32x32), 4 stages
#define BM       64
#define BNT      128
#define BKI      64                      // K elems per iter
#define NIT      (NN / BKI)              // 128
#define PA       4096                    // A digit plane: 64 rows * 64B
#define PB       8192                    // B digit plane: 128 rows * 64B
#define STAGE_SZ (2 * PA + 2 * PB)       // 24576
#define NSTAGE   4
#define DSMEM_MM (NSTAGE * STAGE_SZ)     // 98304 -> 2 CTAs/SM

#define BQ_SCALE 32256.f                 // 126*256: b1 in [-126,126], 15-bit q

// ---------------- scratch ---------------------------------------------------
__device__ float g_x[NN * QH];            // Q-hidden
__device__ float g_h[NN * D2];            // hidden (h1 then h2)
__device__ float g_yT[(size_t)D1 * NN];   // Y^T fp32 [256, 8192]
__device__ int8_t g_B1[(size_t)D1 * NN];  // Y^T digit-1 (s8)
__device__ int8_t g_B2[(size_t)D1 * NN];  // Y^T digit-2 (s8)
__device__ float g_cs[D1];                // per-column scale / (65536*BQ_SCALE)
__device__ float g_part[64 * 2 * D0];
__device__ float g_scale[D0];
__device__ float g_shift[D0];

// ---------------- PTX helpers (baseline ISA) --------------------------------
__device__ __forceinline__ uint32_t smem_u32(const void* p) {
    uint32_t a;
    asm("{ .reg .u64 t; cvta.to.shared.u64 t, %1; cvt.u32.u64 %0, t; }" : "=r"(a) : "l"(p));
    return a;
}
__device__ __forceinline__ void cp_async16(uint32_t dst, const void* src) {
    asm volatile("cp.async.cg.shared.global [%0], [%1], 16;" :: "r"(dst), "l"(src) : "memory");
}
__device__ __forceinline__ void ldsm4(uint32_t& r0, uint32_t& r1, uint32_t& r2, uint32_t& r3,
                                      uint32_t a) {
    asm volatile("ldmatrix.sync.aligned.m8n8.x4.shared.b16 {%0,%1,%2,%3}, [%4];"
                 : "=r"(r0), "=r"(r1), "=r"(r2), "=r"(r3) : "r"(a));
}
// int8 mma: D(s32) += A(u8) * B(s8)
__device__ __forceinline__ void mma_u8s8(int* c, const uint32_t* a, const uint32_t* b) {
    asm volatile("mma.sync.aligned.m16n8k32.row.col.s32.u8.s8.s32 "
                 "{%0,%1,%2,%3}, {%4,%5,%6,%7}, {%8,%9}, {%0,%1,%2,%3};"
                 : "+r"(c[0]), "+r"(c[1]), "+r"(c[2]), "+r"(c[3])
                 : "r"(a[0]), "r"(a[1]), "r"(a[2]), "r"(a[3]), "r"(b[0]), "r"(b[1]));
}
// swizzled 16B-chunk offset within a tile of 64B rows
__device__ __forceinline__ uint32_t swz(uint32_t row, uint32_t chunk) {
    return row * 64u + ((chunk ^ ((row >> 1) & 3u)) << 4);
}

// ---------------- batchnorm stats -> scale/shift -----------------------------
__global__ void bn_partial_kernel(const float* __restrict__ state) {
    int c = threadIdx.x, b = blockIdx.x;
    int r0 = b * (NN / 64);
    float s = 0.f, s2 = 0.f;
    #pragma unroll 4
    for (int r = 0; r < NN / 64; ++r) {
        float v = state[(size_t)(r0 + r) * D0 + c];
        s += v; s2 += v * v;
    }
    g_part[b * 2 * D0 + c]      = s;
    g_part[b * 2 * D0 + D0 + c] = s2;
}
__global__ void bn_final_kernel(const float* __restrict__ gamma,
                                const float* __restrict__ beta) {
    int c = threadIdx.x;
    float s = 0.f, s2 = 0.f;
    #pragma unroll
    for (int b = 0; b < 64; ++b) {
        s  += g_part[b * 2 * D0 + c];
        s2 += g_part[b * 2 * D0 + D0 + c];
    }
    float mean = s * (1.0f / NN);
    float var  = s2 * (1.0f / NN) - mean * mean;
    float sc = rsqrtf(var + EPSV) * gamma[c];
    g_scale[c] = sc;
    g_shift[c] = beta[c] - mean * sc;
}

// ---------------- small SGEMM: optional fused BN on A; TOUT = fp32 Y^T ------
template<bool BIAS, bool RELU, bool DOBN, bool TOUT>
__global__ void __launch_bounds__(256)
sgemm_kernel(const float* __restrict__ A, const float* __restrict__ B,
             const float* __restrict__ bias, float* __restrict__ C,
             float* __restrict__ outT,
             int M, int N, int K) {
    constexpr int TBM = 64, TBN = 64, TBK = 16, TM = 4, TN = 4;
    __shared__ float As[TBK][TBM];
    __shared__ float Bs[TBK][TBN];
    __shared__ uint32_t ts[TOUT ? 64 * 65 : 1];
    const int tid = threadIdx.x;
    const int tx = tid % (TBN / TN);
    const int ty = tid / (TBN / TN);
    const int rowBase = blockIdx.y * TBM;
    const int colBase = blockIdx.x * TBN;
    const int aRow = tid / (TBK / 4);
    const int aCol = (tid % (TBK / 4)) * 4;
    const int bRow = tid / (TBN / 4);
    const int bCol = (tid % (TBN / 4)) * 4;
    float acc[TM][TN] = {};
    for (int k0 = 0; k0 < K; k0 += TBK) {
        float4 av = *(const float4*)(A + (size_t)(rowBase + aRow) * K + k0 + aCol);
        if (DOBN) {
            float4 sc = *(const float4*)(g_scale + k0 + aCol);
            float4 sh = *(const float4*)(g_shift + k0 + aCol);
            av.x = fmaf(av.x, sc.x, sh.x);
            av.y = fmaf(av.y, sc.y, sh.y);
            av.z = fmaf(av.z, sc.z, sh.z);
            av.w = fmaf(av.w, sc.w, sh.w);
        }
        As[aCol + 0][aRow] = av.x; As[aCol + 1][aRow] = av.y;
        As[aCol + 2][aRow] = av.z; As[aCol + 3][aRow] = av.w;
        float4 bv = *(const float4*)(B + (size_t)(k0 + bRow) * N + colBase + bCol);
        *(float4*)&Bs[bRow][bCol] = bv;
        __syncthreads();
        #pragma unroll
        for (int k = 0; k < TBK; ++k) {
            float4 a4 = *(const float4*)&As[k][ty * TM];
            float4 b4 = *(const float4*)&Bs[k][tx * TN];
            float a[TM] = {a4.x, a4.y, a4.z, a4.w};
            float b[TN] = {b4.x, b4.y, b4.z, b4.w};
            #pragma unroll
            for (int i = 0; i < TM; ++i)
                #pragma unroll
                for (int j = 0; j < TN; ++j)
                    acc[i][j] = fmaf(a[i], b[j], acc[i][j]);
        }
        __syncthreads();
    }

    if (!TOUT) {
        #pragma unroll
        for (int i = 0; i < TM; ++i) {
            int r = rowBase + ty * TM + i;
            #pragma unroll
            for (int j = 0; j < TN; ++j) {
                int c = colBase + tx * TN + j;
                float v = acc[i][j];
                if (BIAS) v += bias[c];
                if (RELU) v = fmaxf(v, 0.f);
                C[(size_t)r * N + c] = v;
            }
        }
    } else {
        // transpose via smem, write fp32 Y^T[col][row]
        #pragma unroll
        for (int i = 0; i < TM; ++i)
            #pragma unroll
            for (int j = 0; j < TN; ++j) {
                int cl = tx * TN + j, rl = ty * TM + i;
                ts[cl * 65 + rl] = __float_as_uint(acc[i][j]);
            }
        __syncthreads();
        #pragma unroll
        for (int i = 0; i < 4; ++i) {
            int id = i * 256 + tid;          // 0..1023
            int cl = id >> 4;                // 0..63
            int rp = (id & 15) * 4;
            float4 v;
            v.x = __uint_as_float(ts[cl * 65 + rp + 0]);
            v.y = __uint_as_float(ts[cl * 65 + rp + 1]);
            v.z = __uint_as_float(ts[cl * 65 + rp + 2]);
            v.w = __uint_as_float(ts[cl * 65 + rp + 3]);
            *(float4*)(outT + (size_t)(colBase + cl) * NN + rowBase + rp) = v;
        }
    }
}

// ---------------- Y^T -> per-column scale + 2x s8 digits ---------------------
// One CTA per column. s_c = max|Y^T[c,:]|;  q = rn(Y/s_c * 32256), |q| <= 32256
// digits: b1 = (q+128)>>8 in [-126,126], b2 = q - (b1<<8) in [-128,127].
__global__ void __launch_bounds__(256)
convB_kernel(const float* __restrict__ Y, int8_t* __restrict__ B1,
             int8_t* __restrict__ B2, float* __restrict__ cs) {
    __shared__ float red[8];
    const int c = blockIdx.x;
    const int tid = threadIdx.x;
    const float* y = Y + (size_t)c * NN;
    float m = 0.f;
    for (int i = tid; i < NN; i += 256) m = fmaxf(m, fabsf(y[i]));
    #pragma unroll
    for (int o = 16; o; o >>= 1) m = fmaxf(m, __shfl_xor_sync(0xffffffffu, m, o));
    if ((tid & 31) == 0) red[tid >> 5] = m;
    __syncthreads();
    if (tid < 32) {
        float t = (tid < 8) ? red[tid] : 0.f;
        #pragma unroll
        for (int o = 4; o; o >>= 1) t = fmaxf(t, __shfl_xor_sync(0xffffffffu, t, o));
        if (tid == 0) red[0] = fmaxf(t, 1e-35f);
    }
    __syncthreads();
    const float s = red[0];
    if (tid == 0) cs[c] = s / (65536.f * BQ_SCALE);
    const float inv = BQ_SCALE / s;
    for (int i = tid; i < NN; i += 256) {
        int q = __float2int_rn(y[i] * inv);
        int b1 = (q + 128) >> 8;
        int b2 = q - (b1 << 8);
        B1[(size_t)c * NN + i] = (int8_t)b1;
        B2[(size_t)c * NN + i] = (int8_t)b2;
    }
}

// ---------------- big GEMM: C = relu(A @ Y^T + bias), int8 fixed-point -------
// A fp32 [NN,NN]: in-loop split to u8 digits a1,a2 (q_A = a1*256+a2 = rn(A*65536)).
// B digits s8 [256,NN] (cp.async).  T11=a1b1, Tcr=a1b2+a2b1, T22=a2b2 (all s32).
// Result = (T11*2^16 + Tcr*2^8 + T22) * cs + bias, relu.  EXACT integer product.
// Tile 64x128xK64, 8 warps (32x32), 4-stage swizzled pipeline, 2 CTAs/SM.
__global__ void __launch_bounds__(256, 2)
bigmm_kernel(const float* __restrict__ A,
             const int8_t* __restrict__ B1, const int8_t* __restrict__ B2,
             const float* __restrict__ cs, const float* __restrict__ bias,
             float* __restrict__ C) {
    extern __shared__ char sm[];
    const uint32_t sbase = smem_u32(sm);
    const int tid = threadIdx.x;
    const int n0 = blockIdx.x * BNT;
    const int m0 = blockIdx.y * BM;

    // ---- A loader: 4 threads/row, 16 floats (64B fp32 -> 16B digits) each ----
    const int lrow = tid >> 2, lchk = tid & 3;
    const float* gA = A + (size_t)(m0 + lrow) * NN + lchk * 16;
    const uint32_t swA = swz(lrow, lchk);
    // ---- B loader: 2 threads/row, 2x16B chunks per digit plane ----
    const int brow = tid >> 1, bch = (tid & 1) * 2;
    const int8_t* gB1 = B1 + (size_t)(n0 + brow) * NN + bch * 16;
    const int8_t* gB2 = B2 + (size_t)(n0 + brow) * NN + bch * 16;
    const uint32_t swB0 = swz(brow, bch), swB1 = swz(brow, bch + 1);

    float4 rA[4];
    auto LDG_A = [&](int j) {
        const float* p = gA + (size_t)j * BKI;
        rA[0] = *(const float4*)(p + 0);
        rA[1] = *(const float4*)(p + 4);
        rA[2] = *(const float4*)(p + 8);
        rA[3] = *(const float4*)(p + 12);
    };
    auto STS_A = [&](int s) {
        const float* f = (const float*)rA;
        uint32_t hi[4], lo[4];
        #pragma unroll
        for (int e = 0; e < 4; ++e) {
            uint32_t h = 0, l = 0;
            #pragma unroll
            for (int b = 0; b < 4; ++b) {
                int q = __float2int_rn(f[e * 4 + b] * 65536.f);
                q = min(max(q, 0), 65535);
                h |= (uint32_t)(q >> 8) << (8 * b);
                l |= (uint32_t)(q & 255) << (8 * b);
            }
            hi[e] = h; lo[e] = l;
        }
        char* d = sm + s * STAGE_SZ + swA;
        *(uint4*)(d)      = make_uint4(hi[0], hi[1], hi[2], hi[3]);
        *(uint4*)(d + PA) = make_uint4(lo[0], lo[1], lo[2], lo[3]);
    };
    auto CP_B = [&](int s, int j) {
        uint32_t sb = sbase + s * STAGE_SZ + 2 * PA;
        size_t k = (size_t)j * BKI;
        cp_async16(sb + swB0,      gB1 + k);
        cp_async16(sb + swB1,      gB1 + k + 16);
        cp_async16(sb + PB + swB0, gB2 + k);
        cp_async16(sb + PB + swB1, gB2 + k + 16);
        asm volatile("cp.async.commit_group;" ::: "memory");
    };

    // ---- compute mapping: 8 warps = 2(m) x 4(n), warp tile 32x32 ----
    const int wid = tid >> 5, lane = tid & 31;
    const int wm = wid & 1, wn = wid >> 1;
    const uint32_t rowA0 = wm * 32 + (lane & 15);
    const uint32_t ca    = lane >> 4;               // 0/1
    const uint32_t rowB0 = wn * 32 + ((lane >> 4) << 3) + (lane & 7);
    const uint32_t cb    = (lane >> 3) & 1;

    int acc1[2][4][4], acc2[2][4][4], acc3[2][4][4];
    #pragma unroll
    for (int mt = 0; mt < 2; ++mt)
        #pragma unroll
        for (int nt = 0; nt < 4; ++nt)
            #pragma unroll
            for (int e = 0; e < 4; ++e) {
                acc1[mt][nt][e] = 0; acc2[mt][nt][e] = 0; acc3[mt][nt][e] = 0;
            }

    // ---- prologue ----
    LDG_A(0); STS_A(0); CP_B(0, 0);
    LDG_A(1); STS_A(1); CP_B(1, 1);
    LDG_A(2); STS_A(2); CP_B(2, 2);
    LDG_A(3);

    for (int j = 0; j < NIT; ++j) {
        const int rem = NIT - 1 - j;
        if (rem >= 2)      { asm volatile("cp.async.wait_group 2;" ::: "memory"); }
        else if (rem == 1) { asm volatile("cp.async.wait_group 1;" ::: "memory"); }
        else               { asm volatile("cp.async.wait_group 0;" ::: "memory"); }
        __syncthreads();
        if (j + 3 < NIT) {
            const int ls = (j + 3) & (NSTAGE - 1);
            STS_A(ls);                 // rA holds data for iteration j+3
            CP_B(ls, j + 3);
        }
        if (j + 4 < NIT) LDG_A(j + 4);

        const uint32_t sb  = sbase + (j & (NSTAGE - 1)) * STAGE_SZ;
        const uint32_t sbB = sb + 2 * PA;
        #pragma unroll
        for (int kh = 0; kh < 2; ++kh) {
            uint32_t a1[2][4], a2[2][4], bb[4][2];
            #pragma unroll
            for (int mt = 0; mt < 2; ++mt) {
                uint32_t ad = sb + swz(rowA0 + mt * 16, kh * 2 + ca);
                ldsm4(a1[mt][0], a1[mt][1], a1[mt][2], a1[mt][3], ad);
                ldsm4(a2[mt][0], a2[mt][1], a2[mt][2], a2[mt][3], ad + PA);
            }
            // B digit-1 fragments
            #pragma unroll
            for (int p = 0; p < 2; ++p) {
                uint32_t bd = sbB + swz(rowB0 + p * 16, kh * 2 + cb);
                uint32_t r0, r1, r2, r3;
                ldsm4(r0, r1, r2, r3, bd);
                bb[2 * p][0] = r0; bb[2 * p][1] = r1;
                bb[2 * p + 1][0] = r2; bb[2 * p + 1][1] = r3;
            }
            #pragma unroll
            for (int mt = 0; mt < 2; ++mt)
                #pragma unroll
                for (int nt = 0; nt < 4; ++nt)
                    mma_u8s8(acc1[mt][nt], a1[mt], bb[nt]);     // T11 += a1*b1
            #pragma unroll
            for (int mt = 0; mt < 2; ++mt)
                #pragma unroll
                for (int nt = 0; nt < 4; ++nt)
                    mma_u8s8(acc2[mt][nt], a2[mt], bb[nt]);     // Tcr += a2*b1
            // B digit-2 fragments (reuse bb regs)
            #pragma unroll
            for (int p = 0; p < 2; ++p) {
                uint32_t bd = sbB + PB + swz(rowB0 + p * 16, kh * 2 + cb);
                uint32_t r0, r1, r2, r3;
                ldsm4(r0, r1, r2, r3, bd);
                bb[2 * p][0] = r0; bb[2 * p][1] = r1;
                bb[2 * p + 1][0] = r2; bb[2 * p + 1][1] = r3;
            }
            #pragma unroll
            for (int mt = 0; mt < 2; ++mt)
                #pragma unroll
                for (int nt = 0; nt < 4; ++nt)
                    mma_u8s8(acc2[mt][nt], a1[mt], bb[nt]);     // Tcr += a1*b2
            #pragma unroll
            for (int mt = 0; mt < 2; ++mt)
                #pragma unroll
                for (int nt = 0; nt < 4; ++nt)
                    mma_u8s8(acc3[mt][nt], a2[mt], bb[nt]);     // T22 += a2*b2
        }
    }

    // ---- epilogue: combine digits exactly, scale + bias + relu + store ----
    #pragma unroll
    for (int mt = 0; mt < 2; ++mt) {
        #pragma unroll
        for (int nt = 0; nt < 4; ++nt) {
            int r = m0 + wm * 32 + mt * 16 + (lane >> 2);
            int c = n0 + wn * 32 + nt * 8 + (lane & 3) * 2;
            float cs0 = cs[c], cs1 = cs[c + 1];
            float b0 = bias[c], b1 = bias[c + 1];
            #pragma unroll
            for (int e = 0; e < 4; e += 2) {
                // exact: e = T11*2^16 + Tcr*2^8 + T22 (double avoids fp32 mid-rounding)
                float g0 = fmaf((float)acc1[mt][nt][e], 65536.f,
                         fmaf((float)acc2[mt][nt][e], 256.f, (float)acc3[mt][nt][e]));
                float g1 = fmaf((float)acc1[mt][nt][e + 1], 65536.f,
                         fmaf((float)acc2[mt][nt][e + 1], 256.f, (float)acc3[mt][nt][e + 1]));
                float2 v;
                v.x = fmaxf(fmaf(g0, cs0, b0), 0.f);
                v.y = fmaxf(fmaf(g1, cs1, b1), 0.f);
                *(float2*)(C + (size_t)(r + (e ? 8 : 0)) * 256 + c) = v;
            }
        }
    }
}

// ---------------- final Q output --------------------------------------------
__global__ void qout_kernel(const float* __restrict__ T,
                            const float* __restrict__ Wq2,
                            const float* __restrict__ bq2,
                            float* __restrict__ out) {
    int warp = threadIdx.x >> 5;
    int lane = threadIdx.x & 31;
    int row  = blockIdx.x * 8 + warp;
    const float* t = T + (size_t)row * QH;
    float s = 0.f;
    #pragma unroll
    for (int k = lane; k < QH; k += 32) s += t[k] * Wq2[k];
    #pragma unroll
    for (int o = 16; o; o >>= 1) s += __shfl_xor_sync(0xffffffffu, s, o);
    if (lane == 0) out[row] = s + bq2[0];
}

// ---------------- launcher --------------------------------------------------
extern "C" void kernel_launch(void* const* d_in, const int* in_sizes, int n_in,
                              void* d_out, int out_size) {
    const float* state = (const float*)d_in[0];
    const float* adj   = (const float*)d_in[1];
    const float* gamma = (const float*)d_in[2];
    const float* beta  = (const float*)d_in[3];
    const float* W1    = (const float*)d_in[4];
    const float* b1    = (const float*)d_in[5];
    const float* W2    = (const float*)d_in[6];
    const float* b2    = (const float*)d_in[7];
    const float* Wq1   = (const float*)d_in[8];
    const float* bq1   = (const float*)d_in[9];
    const float* Wq2   = (const float*)d_in[10];
    const float* bq2   = (const float*)d_in[11];
    float* out = (float*)d_out;

    float *gx, *gh, *gyT, *gcs;
    int8_t *gB1, *gB2;
    cudaGetSymbolAddress((void**)&gx, g_x);
    cudaGetSymbolAddress((void**)&gh, g_h);
    cudaGetSymbolAddress((void**)&gyT, g_yT);
    cudaGetSymbolAddress((void**)&gcs, g_cs);
    cudaGetSymbolAddress((void**)&gB1, g_B1);
    cudaGetSymbolAddress((void**)&gB2, g_B2);

    cudaFuncSetAttribute(bigmm_kernel, cudaFuncAttributeMaxDynamicSharedMemorySize, DSMEM_MM);

    // BatchNorm stats -> scale/shift
    bn_partial_kernel<<<64, D0>>>(state);
    bn_final_kernel<<<1, D0>>>(gamma, beta);

    // Y1^T fp32 = (bn(state) @ W1)^T ; then per-column int8 digits
    sgemm_kernel<false, false, true, true>
        <<<dim3(D1 / 64, NN / 64), 256>>>(state, W1, nullptr, nullptr, gyT, NN, D1, D0);
    convB_kernel<<<D1, 256>>>(gyT, gB1, gB2, gcs);

    // h1 = relu(A @ Y1 + b1)   — int8 fixed-point tensor cores
    bigmm_kernel<<<dim3(2, NN / BM), 256, DSMEM_MM>>>(adj, gB1, gB2, gcs, b1, gh);

    // Y2^T fp32 = (h1 @ W2)^T ; digits
    sgemm_kernel<false, false, false, true>
        <<<dim3(D2 / 64, NN / 64), 256>>>(gh, W2, nullptr, nullptr, gyT, NN, D2, D1);
    convB_kernel<<<D2, 256>>>(gyT, gB1, gB2, gcs);

    // h2 = relu(A @ Y2 + b2)
    bigmm_kernel<<<dim3(2, NN / BM), 256, DSMEM_MM>>>(adj, gB1, gB2, gcs, b2, gh);

    // Q head
    sgemm_kernel<true, true, false, false>
        <<<dim3(QH / 64, NN / 64), 256>>>(gh, Wq1, bq1, gx, nullptr, NN, QH, D2);
    qout_kernel<<<NN / 8, 256>>>(gx, Wq2, bq2, out);
}

// round 17
// speedup vs baseline: 1.0226x; 1.0226x over previous
#include <cuda_runtime.h>
#include <cuda_bf16.h>
#include <cstdint>

// Problem dims (fixed)
#define NN   8192
#define D0   128
#define D1   256
#define D2   256
#define QH   128
#define EPSV 1e-5f

// bigmm tiling: CTA 64x64, BK=64, 8 warps (warp tile 32x16), 4 stages
#define BM       64
#define BNT      64
#define BKI      64                      // K elems per iter
#define NIT      (NN / BKI)              // 128
#define PA       4096                    // A digit plane: 64 rows * 64B
#define PB       4096                    // B digit plane: 64 rows * 64B
#define STAGE_SZ (2 * PA + 2 * PB)       // 16384
#define NSTAGE   4
#define DSMEM_MM (NSTAGE * STAGE_SZ)     // 65536 -> 2 CTAs/SM

#define BQ_SCALE 32256.f                 // 126*256: b1 in [-126,126], 15-bit q

// ---------------- scratch ---------------------------------------------------
__device__ float g_x[NN * QH];            // Q-hidden
__device__ float g_h[NN * D2];            // hidden (h1 then h2)
__device__ float g_yT[(size_t)D1 * NN];   // Y^T fp32 [256, 8192]
__device__ int8_t g_B1[(size_t)D1 * NN];  // Y^T digit-1 (s8)
__device__ int8_t g_B2[(size_t)D1 * NN];  // Y^T digit-2 (s8)
__device__ float g_cs[D1];                // per-column scale / (65536*BQ_SCALE)
__device__ float g_part[64 * 2 * D0];
__device__ float g_scale[D0];
__device__ float g_shift[D0];

// ---------------- PTX helpers (baseline ISA) --------------------------------
__device__ __forceinline__ uint32_t smem_u32(const void* p) {
    uint32_t a;
    asm("{ .reg .u64 t; cvta.to.shared.u64 t, %1; cvt.u32.u64 %0, t; }" : "=r"(a) : "l"(p));
    return a;
}
__device__ __forceinline__ void cp_async16(uint32_t dst, const void* src) {
    asm volatile("cp.async.cg.shared.global [%0], [%1], 16;" :: "r"(dst), "l"(src) : "memory");
}
__device__ __forceinline__ void ldsm4(uint32_t& r0, uint32_t& r1, uint32_t& r2, uint32_t& r3,
                                      uint32_t a) {
    asm volatile("ldmatrix.sync.aligned.m8n8.x4.shared.b16 {%0,%1,%2,%3}, [%4];"
                 : "=r"(r0), "=r"(r1), "=r"(r2), "=r"(r3) : "r"(a));
}
// int8 mma: D(s32) += A(u8) * B(s8)
__device__ __forceinline__ void mma_u8s8(int* c, const uint32_t* a, const uint32_t* b) {
    asm volatile("mma.sync.aligned.m16n8k32.row.col.s32.u8.s8.s32 "
                 "{%0,%1,%2,%3}, {%4,%5,%6,%7}, {%8,%9}, {%0,%1,%2,%3};"
                 : "+r"(c[0]), "+r"(c[1]), "+r"(c[2]), "+r"(c[3])
                 : "r"(a[0]), "r"(a[1]), "r"(a[2]), "r"(a[3]), "r"(b[0]), "r"(b[1]));
}
// swizzled 16B-chunk offset within a tile of 64B rows
__device__ __forceinline__ uint32_t swz(uint32_t row, uint32_t chunk) {
    return row * 64u + ((chunk ^ ((row >> 1) & 3u)) << 4);
}

// ---------------- batchnorm stats -> scale/shift -----------------------------
__global__ void bn_partial_kernel(const float* __restrict__ state) {
    int c = threadIdx.x, b = blockIdx.x;
    int r0 = b * (NN / 64);
    float s = 0.f, s2 = 0.f;
    #pragma unroll 4
    for (int r = 0; r < NN / 64; ++r) {
        float v = state[(size_t)(r0 + r) * D0 + c];
        s += v; s2 += v * v;
    }
    g_part[b * 2 * D0 + c]      = s;
    g_part[b * 2 * D0 + D0 + c] = s2;
}
__global__ void bn_final_kernel(const float* __restrict__ gamma,
                                const float* __restrict__ beta) {
    int c = threadIdx.x;
    float s = 0.f, s2 = 0.f;
    #pragma unroll
    for (int b = 0; b < 64; ++b) {
        s  += g_part[b * 2 * D0 + c];
        s2 += g_part[b * 2 * D0 + D0 + c];
    }
    float mean = s * (1.0f / NN);
    float var  = s2 * (1.0f / NN) - mean * mean;
    float sc = rsqrtf(var + EPSV) * gamma[c];
    g_scale[c] = sc;
    g_shift[c] = beta[c] - mean * sc;
}

// ---------------- small SGEMM: optional fused BN on A; TOUT = fp32 Y^T ------
template<bool BIAS, bool RELU, bool DOBN, bool TOUT>
__global__ void __launch_bounds__(256)
sgemm_kernel(const float* __restrict__ A, const float* __restrict__ B,
             const float* __restrict__ bias, float* __restrict__ C,
             float* __restrict__ outT,
             int M, int N, int K) {
    constexpr int TBM = 64, TBN = 64, TBK = 16, TM = 4, TN = 4;
    __shared__ float As[TBK][TBM];
    __shared__ float Bs[TBK][TBN];
    __shared__ uint32_t ts[TOUT ? 64 * 65 : 1];
    const int tid = threadIdx.x;
    const int tx = tid % (TBN / TN);
    const int ty = tid / (TBN / TN);
    const int rowBase = blockIdx.y * TBM;
    const int colBase = blockIdx.x * TBN;
    const int aRow = tid / (TBK / 4);
    const int aCol = (tid % (TBK / 4)) * 4;
    const int bRow = tid / (TBN / 4);
    const int bCol = (tid % (TBN / 4)) * 4;
    float acc[TM][TN] = {};
    for (int k0 = 0; k0 < K; k0 += TBK) {
        float4 av = *(const float4*)(A + (size_t)(rowBase + aRow) * K + k0 + aCol);
        if (DOBN) {
            float4 sc = *(const float4*)(g_scale + k0 + aCol);
            float4 sh = *(const float4*)(g_shift + k0 + aCol);
            av.x = fmaf(av.x, sc.x, sh.x);
            av.y = fmaf(av.y, sc.y, sh.y);
            av.z = fmaf(av.z, sc.z, sh.z);
            av.w = fmaf(av.w, sc.w, sh.w);
        }
        As[aCol + 0][aRow] = av.x; As[aCol + 1][aRow] = av.y;
        As[aCol + 2][aRow] = av.z; As[aCol + 3][aRow] = av.w;
        float4 bv = *(const float4*)(B + (size_t)(k0 + bRow) * N + colBase + bCol);
        *(float4*)&Bs[bRow][bCol] = bv;
        __syncthreads();
        #pragma unroll
        for (int k = 0; k < TBK; ++k) {
            float4 a4 = *(const float4*)&As[k][ty * TM];
            float4 b4 = *(const float4*)&Bs[k][tx * TN];
            float a[TM] = {a4.x, a4.y, a4.z, a4.w};
            float b[TN] = {b4.x, b4.y, b4.z, b4.w};
            #pragma unroll
            for (int i = 0; i < TM; ++i)
                #pragma unroll
                for (int j = 0; j < TN; ++j)
                    acc[i][j] = fmaf(a[i], b[j], acc[i][j]);
        }
        __syncthreads();
    }

    if (!TOUT) {
        #pragma unroll
        for (int i = 0; i < TM; ++i) {
            int r = rowBase + ty * TM + i;
            #pragma unroll
            for (int j = 0; j < TN; ++j) {
                int c = colBase + tx * TN + j;
                float v = acc[i][j];
                if (BIAS) v += bias[c];
                if (RELU) v = fmaxf(v, 0.f);
                C[(size_t)r * N + c] = v;
            }
        }
    } else {
        // transpose via smem, write fp32 Y^T[col][row]
        #pragma unroll
        for (int i = 0; i < TM; ++i)
            #pragma unroll
            for (int j = 0; j < TN; ++j) {
                int cl = tx * TN + j, rl = ty * TM + i;
                ts[cl * 65 + rl] = __float_as_uint(acc[i][j]);
            }
        __syncthreads();
        #pragma unroll
        for (int i = 0; i < 4; ++i) {
            int id = i * 256 + tid;          // 0..1023
            int cl = id >> 4;                // 0..63
            int rp = (id & 15) * 4;
            float4 v;
            v.x = __uint_as_float(ts[cl * 65 + rp + 0]);
            v.y = __uint_as_float(ts[cl * 65 + rp + 1]);
            v.z = __uint_as_float(ts[cl * 65 + rp + 2]);
            v.w = __uint_as_float(ts[cl * 65 + rp + 3]);
            *(float4*)(outT + (size_t)(colBase + cl) * NN + rowBase + rp) = v;
        }
    }
}

// ---------------- Y^T -> per-column scale + 2x s8 digits ---------------------
__global__ void __launch_bounds__(256)
convB_kernel(const float* __restrict__ Y, int8_t* __restrict__ B1,
             int8_t* __restrict__ B2, float* __restrict__ cs) {
    __shared__ float red[8];
    const int c = blockIdx.x;
    const int tid = threadIdx.x;
    const float* y = Y + (size_t)c * NN;
    float m = 0.f;
    for (int i = tid; i < NN; i += 256) m = fmaxf(m, fabsf(y[i]));
    #pragma unroll
    for (int o = 16; o; o >>= 1) m = fmaxf(m, __shfl_xor_sync(0xffffffffu, m, o));
    if ((tid & 31) == 0) red[tid >> 5] = m;
    __syncthreads();
    if (tid < 32) {
        float t = (tid < 8) ? red[tid] : 0.f;
        #pragma unroll
        for (int o = 4; o; o >>= 1) t = fmaxf(t, __shfl_xor_sync(0xffffffffu, t, o));
        if (tid == 0) red[0] = fmaxf(t, 1e-35f);
    }
    __syncthreads();
    const float s = red[0];
    if (tid == 0) cs[c] = s / (65536.f * BQ_SCALE);
    const float inv = BQ_SCALE / s;
    for (int i = tid; i < NN; i += 256) {
        int q = __float2int_rn(y[i] * inv);
        int b1 = (q + 128) >> 8;
        int b2 = q - (b1 << 8);
        B1[(size_t)c * NN + i] = (int8_t)b1;
        B2[(size_t)c * NN + i] = (int8_t)b2;
    }
}

// ---------------- big GEMM: C = relu(A @ Y^T + bias), int8 fixed-point -------
// A fp32 [NN,NN]: in-loop split to u8 digits a1,a2 (q_A = a1*256+a2 = rn(A*65536)).
// B digits s8 [256,NN] (cp.async).  T11=a1b1, Tcr=a1b2+a2b1, T22=a2b2 (all s32).
// Result = (T11*2^16 + Tcr*2^8 + T22) * cs + bias, relu.  EXACT integer product.
// CTA tile 64x64xK64, 8 warps (warp tile 32x16), 4-stage pipeline, 2 CTAs/SM.
__global__ void __launch_bounds__(256, 2)
bigmm_kernel(const float* __restrict__ A,
             const int8_t* __restrict__ B1, const int8_t* __restrict__ B2,
             const float* __restrict__ cs, const float* __restrict__ bias,
             float* __restrict__ C) {
    extern __shared__ char sm[];
    const uint32_t sbase = smem_u32(sm);
    const int tid = threadIdx.x;
    const int n0 = blockIdx.x * BNT;
    const int m0 = blockIdx.y * BM;

    // ---- A loader: 4 threads/row, 16 floats (64B fp32 -> 16B digits) each ----
    const int lrow = tid >> 2, lchk = tid & 3;
    const float* gA = A + (size_t)(m0 + lrow) * NN + lchk * 16;
    const uint32_t swA = swz(lrow, lchk);
    // ---- B loader: 4 threads/row (64 rows), one 16B chunk per digit plane ----
    const int brow = tid >> 2, bch = tid & 3;
    const int8_t* gB1 = B1 + (size_t)(n0 + brow) * NN + bch * 16;
    const int8_t* gB2 = B2 + (size_t)(n0 + brow) * NN + bch * 16;
    const uint32_t swB = swz(brow, bch);

    float4 rA[4];
    auto LDG_A = [&](int j) {
        const float* p = gA + (size_t)j * BKI;
        rA[0] = *(const float4*)(p + 0);
        rA[1] = *(const float4*)(p + 4);
        rA[2] = *(const float4*)(p + 8);
        rA[3] = *(const float4*)(p + 12);
    };
    auto STS_A = [&](int s) {
        const float* f = (const float*)rA;
        uint32_t hi[4], lo[4];
        #pragma unroll
        for (int e = 0; e < 4; ++e) {
            uint32_t h = 0, l = 0;
            #pragma unroll
            for (int b = 0; b < 4; ++b) {
                int q = __float2int_rn(f[e * 4 + b] * 65536.f);
                q = min(max(q, 0), 65535);
                h |= (uint32_t)(q >> 8) << (8 * b);
                l |= (uint32_t)(q & 255) << (8 * b);
            }
            hi[e] = h; lo[e] = l;
        }
        char* d = sm + s * STAGE_SZ + swA;
        *(uint4*)(d)      = make_uint4(hi[0], hi[1], hi[2], hi[3]);
        *(uint4*)(d + PA) = make_uint4(lo[0], lo[1], lo[2], lo[3]);
    };
    auto CP_B = [&](int s, int j) {
        uint32_t sb = sbase + s * STAGE_SZ + 2 * PA;
        size_t k = (size_t)j * BKI;
        cp_async16(sb + swB,      gB1 + k);
        cp_async16(sb + PB + swB, gB2 + k);
        asm volatile("cp.async.commit_group;" ::: "memory");
    };

    // ---- compute mapping: 8 warps = 2(m) x 4(n), warp tile 32x16 ----
    const int wid = tid >> 5, lane = tid & 31;
    const int wm = wid & 1, wn = wid >> 1;          // wn 0..3
    const uint32_t rowA0 = wm * 32 + (lane & 15);
    const uint32_t ca    = lane >> 4;               // 0/1
    const uint32_t rowB0 = wn * 16 + ((lane >> 4) << 3) + (lane & 7);
    const uint32_t cb    = (lane >> 3) & 1;

    int acc1[2][2][4], acc2[2][2][4], acc3[2][2][4];
    #pragma unroll
    for (int mt = 0; mt < 2; ++mt)
        #pragma unroll
        for (int nt = 0; nt < 2; ++nt)
            #pragma unroll
            for (int e = 0; e < 4; ++e) {
                acc1[mt][nt][e] = 0; acc2[mt][nt][e] = 0; acc3[mt][nt][e] = 0;
            }

    // ---- prologue ----
    LDG_A(0); STS_A(0); CP_B(0, 0);
    LDG_A(1); STS_A(1); CP_B(1, 1);
    LDG_A(2); STS_A(2); CP_B(2, 2);
    LDG_A(3);

    for (int j = 0; j < NIT; ++j) {
        const int rem = NIT - 1 - j;
        if (rem >= 2)      { asm volatile("cp.async.wait_group 2;" ::: "memory"); }
        else if (rem == 1) { asm volatile("cp.async.wait_group 1;" ::: "memory"); }
        else               { asm volatile("cp.async.wait_group 0;" ::: "memory"); }
        __syncthreads();
        if (j + 3 < NIT) {
            const int ls = (j + 3) & (NSTAGE - 1);
            STS_A(ls);                 // rA holds data for iteration j+3
            CP_B(ls, j + 3);
        }
        if (j + 4 < NIT) LDG_A(j + 4);

        const uint32_t sb  = sbase + (j & (NSTAGE - 1)) * STAGE_SZ;
        const uint32_t sbB = sb + 2 * PA;
        #pragma unroll
        for (int kh = 0; kh < 2; ++kh) {
            uint32_t a1[2][4], a2[2][4], bb[2][2];
            #pragma unroll
            for (int mt = 0; mt < 2; ++mt) {
                uint32_t ad = sb + swz(rowA0 + mt * 16, kh * 2 + ca);
                ldsm4(a1[mt][0], a1[mt][1], a1[mt][2], a1[mt][3], ad);
                ldsm4(a2[mt][0], a2[mt][1], a2[mt][2], a2[mt][3], ad + PA);
            }
            // B digit-1 fragments (one ldsm.x4 covers both 8-col tiles)
            {
                uint32_t r0, r1, r2, r3;
                ldsm4(r0, r1, r2, r3, sbB + swz(rowB0, kh * 2 + cb));
                bb[0][0] = r0; bb[0][1] = r1; bb[1][0] = r2; bb[1][1] = r3;
            }
            #pragma unroll
            for (int mt = 0; mt < 2; ++mt)
                #pragma unroll
                for (int nt = 0; nt < 2; ++nt)
                    mma_u8s8(acc1[mt][nt], a1[mt], bb[nt]);     // T11 += a1*b1
            #pragma unroll
            for (int mt = 0; mt < 2; ++mt)
                #pragma unroll
                for (int nt = 0; nt < 2; ++nt)
                    mma_u8s8(acc2[mt][nt], a2[mt], bb[nt]);     // Tcr += a2*b1
            // B digit-2 fragments (reuse bb regs)
            {
                uint32_t r0, r1, r2, r3;
                ldsm4(r0, r1, r2, r3, sbB + PB + swz(rowB0, kh * 2 + cb));
                bb[0][0] = r0; bb[0][1] = r1; bb[1][0] = r2; bb[1][1] = r3;
            }
            #pragma unroll
            for (int mt = 0; mt < 2; ++mt)
                #pragma unroll
                for (int nt = 0; nt < 2; ++nt)
                    mma_u8s8(acc2[mt][nt], a1[mt], bb[nt]);     // Tcr += a1*b2
            #pragma unroll
            for (int mt = 0; mt < 2; ++mt)
                #pragma unroll
                for (int nt = 0; nt < 2; ++nt)
                    mma_u8s8(acc3[mt][nt], a2[mt], bb[nt]);     // T22 += a2*b2
        }
    }

    // ---- epilogue: combine digits exactly, scale + bias + relu + store ----
    #pragma unroll
    for (int mt = 0; mt < 2; ++mt) {
        #pragma unroll
        for (int nt = 0; nt < 2; ++nt) {
            int r = m0 + wm * 32 + mt * 16 + (lane >> 2);
            int c = n0 + wn * 16 + nt * 8 + (lane & 3) * 2;
            float cs0 = cs[c], cs1 = cs[c + 1];
            float b0 = bias[c], b1 = bias[c + 1];
            #pragma unroll
            for (int e = 0; e < 4; e += 2) {
                float g0 = fmaf((float)acc1[mt][nt][e], 65536.f,
                         fmaf((float)acc2[mt][nt][e], 256.f, (float)acc3[mt][nt][e]));
                float g1 = fmaf((float)acc1[mt][nt][e + 1], 65536.f,
                         fmaf((float)acc2[mt][nt][e + 1], 256.f, (float)acc3[mt][nt][e + 1]));
                float2 v;
                v.x = fmaxf(fmaf(g0, cs0, b0), 0.f);
                v.y = fmaxf(fmaf(g1, cs1, b1), 0.f);
                *(float2*)(C + (size_t)(r + (e ? 8 : 0)) * 256 + c) = v;
            }
        }
    }
}

// ---------------- final Q output --------------------------------------------
__global__ void qout_kernel(const float* __restrict__ T,
                            const float* __restrict__ Wq2,
                            const float* __restrict__ bq2,
                            float* __restrict__ out) {
    int warp = threadIdx.x >> 5;
    int lane = threadIdx.x & 31;
    int row  = blockIdx.x * 8 + warp;
    const float* t = T + (size_t)row * QH;
    float s = 0.f;
    #pragma unroll
    for (int k = lane; k < QH; k += 32) s += t[k] * Wq2[k];
    #pragma unroll
    for (int o = 16; o; o >>= 1) s += __shfl_xor_sync(0xffffffffu, s, o);
    if (lane == 0) out[row] = s + bq2[0];
}

// ---------------- launcher --------------------------------------------------
extern "C" void kernel_launch(void* const* d_in, const int* in_sizes, int n_in,
                              void* d_out, int out_size) {
    const float* state = (const float*)d_in[0];
    const float* adj   = (const float*)d_in[1];
    const float* gamma = (const float*)d_in[2];
    const float* beta  = (const float*)d_in[3];
    const float* W1    = (const float*)d_in[4];
    const float* b1    = (const float*)d_in[5];
    const float* W2    = (const float*)d_in[6];
    const float* b2    = (const float*)d_in[7];
    const float* Wq1   = (const float*)d_in[8];
    const float* bq1   = (const float*)d_in[9];
    const float* Wq2   = (const float*)d_in[10];
    const float* bq2   = (const float*)d_in[11];
    float* out = (float*)d_out;

    float *gx, *gh, *gyT, *gcs;
    int8_t *gB1, *gB2;
    cudaGetSymbolAddress((void**)&gx, g_x);
    cudaGetSymbolAddress((void**)&gh, g_h);
    cudaGetSymbolAddress((void**)&gyT, g_yT);
    cudaGetSymbolAddress((void**)&gcs, g_cs);
    cudaGetSymbolAddress((void**)&gB1, g_B1);
    cudaGetSymbolAddress((void**)&gB2, g_B2);

    cudaFuncSetAttribute(bigmm_kernel, cudaFuncAttributeMaxDynamicSharedMemorySize, DSMEM_MM);

    // BatchNorm stats -> scale/shift
    bn_partial_kernel<<<64, D0>>>(state);
    bn_final_kernel<<<1, D0>>>(gamma, beta);

    // Y1^T fp32 = (bn(state) @ W1)^T ; then per-column int8 digits
    sgemm_kernel<false, false, true, true>
        <<<dim3(D1 / 64, NN / 64), 256>>>(state, W1, nullptr, nullptr, gyT, NN, D1, D0);
    convB_kernel<<<D1, 256>>>(gyT, gB1, gB2, gcs);

    // h1 = relu(A @ Y1 + b1)   — int8 fixed-point tensor cores
    bigmm_kernel<<<dim3(NN / BNT / 32, NN / BM), 256, DSMEM_MM>>>(adj, gB1, gB2, gcs, b1, gh);

    // Y2^T fp32 = (h1 @ W2)^T ; digits
    sgemm_kernel<false, false, false, true>
        <<<dim3(D2 / 64, NN / 64), 256>>>(gh, W2, nullptr, nullptr, gyT, NN, D2, D1);
    convB_kernel<<<D2, 256>>>(gyT, gB1, gB2, gcs);

    // h2 = relu(A @ Y2 + b2)
    bigmm_kernel<<<dim3(NN / BNT / 32, NN / BM), 256, DSMEM_MM>>>(adj, gB1, gB2, gcs, b2, gh);

    // Q head
    sgemm_kernel<true, true, false, false>
        <<<dim3(QH / 64, NN / 64), 256>>>(gh, Wq1, bq1, gx, nullptr, NN, QH, D2);
    qout_kernel<<<NN / 8, 256>>>(gx, Wq2, bq2, out);
}